// round 3
// baseline (speedup 1.0000x reference)
#include <cuda_runtime.h>
#include <cstdint>

#define N_IN   256
#define N_OUT  64
#define MAXN   100000
#define MAXE   1600000

// Scratch (allocation-free rule: __device__ globals). float4 => 16B aligned.
__device__ float4 g_bufA[(size_t)MAXN * N_OUT / 4];
__device__ float4 g_bufB[(size_t)MAXN * N_OUT / 4];
__device__ int    g_rows[MAXE];
__device__ int    g_cols[MAXE];
__device__ int    g_is64;

// ---------------------------------------------------------------------------
// Detect whether adj_index buffer holds int64 or int32 values.
// For little-endian int64 values < 2^32, every odd 32-bit word is zero.
// For int32 data, odd words are random node indices (all-zero ~ impossible).
// Reads only the first 1KB (in bounds for either layout).
// ---------------------------------------------------------------------------
__global__ void detect_dtype_kernel(const unsigned int* __restrict__ adj_words)
{
    unsigned int acc = 0;
    #pragma unroll
    for (int i = 1; i < 256; i += 2) acc |= adj_words[i];
    g_is64 = (acc == 0) ? 1 : 0;
}

// ---------------------------------------------------------------------------
// Decode adj_index ([2,E], int64 OR int32) into int32 g_rows / g_cols.
// ---------------------------------------------------------------------------
__global__ void __launch_bounds__(256) decode_kernel(const void* __restrict__ adj, int E)
{
    int i = blockIdx.x * blockDim.x + threadIdx.x;
    if (i >= E) return;
    if (g_is64) {
        const long long* a = (const long long*)adj;
        g_rows[i] = (int)a[i];
        g_cols[i] = (int)a[(size_t)E + i];
    } else {
        const int* a = (const int*)adj;
        g_rows[i] = a[i];
        g_cols[i] = a[E + i];
    }
}

// ---------------------------------------------------------------------------
// Dense transform: out = relu(X @ W + bias)
// 64x64 output tile per block, K tiled by 64, static smem (~33KB),
// 256 threads, 4x4 accumulators per thread.
// ---------------------------------------------------------------------------
#define KC 64
#define XPAD 68

__global__ void __launch_bounds__(256) gemm_bias_relu_kernel(
    const float* __restrict__ X, const float* __restrict__ W,
    const float* __restrict__ bias, float4* __restrict__ out, int N)
{
    __shared__ float sW[KC * N_OUT];
    __shared__ float sX[64 * XPAD];

    const int tid  = threadIdx.x;
    const int row0 = blockIdx.x * 64;

    const int cx = tid & 15;
    const int ry = tid >> 4;

    float acc[4][4];
    #pragma unroll
    for (int i = 0; i < 4; i++)
        #pragma unroll
        for (int j = 0; j < 4; j++) acc[i][j] = 0.f;

    for (int k0 = 0; k0 < N_IN; k0 += KC) {
        #pragma unroll
        for (int i = tid; i < (KC * N_OUT) / 4; i += 256)
            ((float4*)sW)[i] = ((const float4*)(W + (size_t)k0 * N_OUT))[i];

        #pragma unroll
        for (int i = tid; i < 64 * 16; i += 256) {
            int r  = i >> 4;
            int kk = i & 15;
            float4 v = make_float4(0.f, 0.f, 0.f, 0.f);
            int row = row0 + r;
            if (row < N)
                v = ((const float4*)(X + (size_t)row * N_IN + k0))[kk];
            *((float4*)(sX + r * XPAD + kk * 4)) = v;
        }
        __syncthreads();

        const float* f0 = sX + (ry * 4 + 0) * XPAD;
        const float* f1 = sX + (ry * 4 + 1) * XPAD;
        const float* f2 = sX + (ry * 4 + 2) * XPAD;
        const float* f3 = sX + (ry * 4 + 3) * XPAD;

        #pragma unroll 8
        for (int k = 0; k < KC; k++) {
            float4 w = *(((const float4*)(sW + k * N_OUT)) + cx);
            float fa = f0[k], fb = f1[k], fc = f2[k], fd = f3[k];
            acc[0][0] += fa * w.x; acc[0][1] += fa * w.y; acc[0][2] += fa * w.z; acc[0][3] += fa * w.w;
            acc[1][0] += fb * w.x; acc[1][1] += fb * w.y; acc[1][2] += fb * w.z; acc[1][3] += fb * w.w;
            acc[2][0] += fc * w.x; acc[2][1] += fc * w.y; acc[2][2] += fc * w.z; acc[2][3] += fc * w.w;
            acc[3][0] += fd * w.x; acc[3][1] += fd * w.y; acc[3][2] += fd * w.z; acc[3][3] += fd * w.w;
        }
        __syncthreads();
    }

    float4 bb = ((const float4*)bias)[cx];
    #pragma unroll
    for (int i = 0; i < 4; i++) {
        int row = row0 + ry * 4 + i;
        if (row < N) {
            float4 o;
            o.x = fmaxf(acc[i][0] + bb.x, 0.f);
            o.y = fmaxf(acc[i][1] + bb.y, 0.f);
            o.z = fmaxf(acc[i][2] + bb.z, 0.f);
            o.w = fmaxf(acc[i][3] + bb.w, 0.f);
            out[(size_t)row * (N_OUT / 4) + cx] = o;
        }
    }
}

// ---------------------------------------------------------------------------
// COO SpMM: dst[rows[e]] += vals[e] * src[cols[e]]   (dst pre-zeroed)
// 16 threads per edge (float4 across 64 channels), 16 edges per block.
// Scatter via red.global.add.v4.f32.
// ---------------------------------------------------------------------------
__global__ void __launch_bounds__(256) spmm_coo_kernel(
    const float* __restrict__ vals, const float4* __restrict__ src,
    float4* __restrict__ dst, int E)
{
    const int tid = threadIdx.x;
    const int le  = tid >> 4;                 // local edge 0..15
    const int ch  = tid & 15;                 // float4 channel 0..15
    const int e   = blockIdx.x * 16 + le;
    if (e >= E) return;

    const int   r = g_rows[e];
    const int   c = g_cols[e];
    const float v = vals[e];

    float4 b  = src[(size_t)c * (N_OUT / 4) + ch];
    float4* d = dst + (size_t)r * (N_OUT / 4) + ch;
    asm volatile(
        "red.global.add.v4.f32 [%0], {%1, %2, %3, %4};"
        :: "l"(d), "f"(v * b.x), "f"(v * b.y), "f"(v * b.z), "f"(v * b.w)
        : "memory");
}

// ---------------------------------------------------------------------------
// kernel_launch: detect -> decode -> GEMM -> (zero, SpMM) x3 ping-pong.
// Graph-capturable, allocation-free.
// ---------------------------------------------------------------------------
extern "C" void kernel_launch(void* const* d_in, const int* in_sizes, int n_in,
                              void* d_out, int out_size)
{
    const void*  adj  = d_in[0];                 // [2, E] int64 OR int32
    const float* vals = (const float*)d_in[1];   // [E]
    const float* X    = (const float*)d_in[2];   // [N, 256]
    const float* W    = (const float*)d_in[3];   // [256, 64]
    const float* bias = (const float*)d_in[4];   // [1, 64]
    float4*      out  = (float4*)d_out;          // [N, 64] fp32

    const int E = in_sizes[0] / 2;
    const int N = in_sizes[2] / N_IN;

    float4* bufA = nullptr;
    float4* bufB = nullptr;
    cudaGetSymbolAddress((void**)&bufA, g_bufA);
    cudaGetSymbolAddress((void**)&bufB, g_bufB);

    const size_t feat_bytes = (size_t)N * N_OUT * sizeof(float);

    // 0) dtype detect + index decode
    detect_dtype_kernel<<<1, 1>>>((const unsigned int*)adj);
    decode_kernel<<<(E + 255) / 256, 256>>>(adj, E);

    // 1) base = relu(X @ W + b) -> bufA
    gemm_bias_relu_kernel<<<(N + 63) / 64, 256>>>(X, W, bias, bufA, N);

    const int spmm_blocks = (E + 15) / 16;

    // 2) hop 1: bufA -> bufB
    cudaMemsetAsync(bufB, 0, feat_bytes, 0);
    spmm_coo_kernel<<<spmm_blocks, 256>>>(vals, bufA, bufB, E);

    // 3) hop 2: bufB -> bufA
    cudaMemsetAsync(bufA, 0, feat_bytes, 0);
    spmm_coo_kernel<<<spmm_blocks, 256>>>(vals, bufB, bufA, E);

    // 4) hop 3: bufA -> d_out
    cudaMemsetAsync(out, 0, feat_bytes, 0);
    spmm_coo_kernel<<<spmm_blocks, 256>>>(vals, bufA, out, E);
}

// round 4
// speedup vs baseline: 1.1361x; 1.1361x over previous
#include <cuda_runtime.h>
#include <cstdint>

#define N_IN   256
#define N_OUT  64
#define MAXN   100000
#define MAXE   1600000

// Scratch (allocation-free rule: __device__ globals). float4 => 16B aligned.
__device__ float4 g_bufA[(size_t)MAXN * N_OUT / 4];
__device__ float4 g_bufB[(size_t)MAXN * N_OUT / 4];
__device__ int    g_rows[MAXE];
__device__ int    g_cols[MAXE];
__device__ int    g_is64;

// ---------------------------------------------------------------------------
// Detect whether adj_index buffer holds int64 or int32 values.
// For little-endian int64 values < 2^32, every odd 32-bit word is zero.
// ---------------------------------------------------------------------------
__global__ void detect_dtype_kernel(const unsigned int* __restrict__ adj_words)
{
    unsigned int acc = 0;
    #pragma unroll
    for (int i = 1; i < 256; i += 2) acc |= adj_words[i];
    g_is64 = (acc == 0) ? 1 : 0;
}

// ---------------------------------------------------------------------------
// Decode adj_index ([2,E], int64 OR int32) into int32 g_rows / g_cols.
// ---------------------------------------------------------------------------
__global__ void __launch_bounds__(256) decode_kernel(const void* __restrict__ adj, int E)
{
    int i = blockIdx.x * blockDim.x + threadIdx.x;
    if (i >= E) return;
    if (g_is64) {
        const long long* a = (const long long*)adj;
        g_rows[i] = (int)a[i];
        g_cols[i] = (int)a[(size_t)E + i];
    } else {
        const int* a = (const int*)adj;
        g_rows[i] = a[i];
        g_cols[i] = a[E + i];
    }
}

// ---------------------------------------------------------------------------
// Dense transform: out = relu(X @ W + bias)
// 64x64 output tile per block, K tiled by 64, static smem (~33KB),
// 256 threads, 4x4 accumulators per thread. FFMA-issue-bound (~80us).
// ---------------------------------------------------------------------------
#define KC 64
#define XPAD 68

__global__ void __launch_bounds__(256) gemm_bias_relu_kernel(
    const float* __restrict__ X, const float* __restrict__ W,
    const float* __restrict__ bias, float4* __restrict__ out, int N)
{
    __shared__ float sW[KC * N_OUT];
    __shared__ float sX[64 * XPAD];

    const int tid  = threadIdx.x;
    const int row0 = blockIdx.x * 64;

    const int cx = tid & 15;
    const int ry = tid >> 4;

    float acc[4][4];
    #pragma unroll
    for (int i = 0; i < 4; i++)
        #pragma unroll
        for (int j = 0; j < 4; j++) acc[i][j] = 0.f;

    for (int k0 = 0; k0 < N_IN; k0 += KC) {
        #pragma unroll
        for (int i = tid; i < (KC * N_OUT) / 4; i += 256)
            ((float4*)sW)[i] = ((const float4*)(W + (size_t)k0 * N_OUT))[i];

        #pragma unroll
        for (int i = tid; i < 64 * 16; i += 256) {
            int r  = i >> 4;
            int kk = i & 15;
            float4 v = make_float4(0.f, 0.f, 0.f, 0.f);
            int row = row0 + r;
            if (row < N)
                v = ((const float4*)(X + (size_t)row * N_IN + k0))[kk];
            *((float4*)(sX + r * XPAD + kk * 4)) = v;
        }
        __syncthreads();

        const float* f0 = sX + (ry * 4 + 0) * XPAD;
        const float* f1 = sX + (ry * 4 + 1) * XPAD;
        const float* f2 = sX + (ry * 4 + 2) * XPAD;
        const float* f3 = sX + (ry * 4 + 3) * XPAD;

        #pragma unroll 8
        for (int k = 0; k < KC; k++) {
            float4 w = *(((const float4*)(sW + k * N_OUT)) + cx);
            float fa = f0[k], fb = f1[k], fc = f2[k], fd = f3[k];
            acc[0][0] += fa * w.x; acc[0][1] += fa * w.y; acc[0][2] += fa * w.z; acc[0][3] += fa * w.w;
            acc[1][0] += fb * w.x; acc[1][1] += fb * w.y; acc[1][2] += fb * w.z; acc[1][3] += fb * w.w;
            acc[2][0] += fc * w.x; acc[2][1] += fc * w.y; acc[2][2] += fc * w.z; acc[2][3] += fc * w.w;
            acc[3][0] += fd * w.x; acc[3][1] += fd * w.y; acc[3][2] += fd * w.z; acc[3][3] += fd * w.w;
        }
        __syncthreads();
    }

    float4 bb = ((const float4*)bias)[cx];
    #pragma unroll
    for (int i = 0; i < 4; i++) {
        int row = row0 + ry * 4 + i;
        if (row < N) {
            float4 o;
            o.x = fmaxf(acc[i][0] + bb.x, 0.f);
            o.y = fmaxf(acc[i][1] + bb.y, 0.f);
            o.z = fmaxf(acc[i][2] + bb.z, 0.f);
            o.w = fmaxf(acc[i][3] + bb.w, 0.f);
            out[(size_t)row * (N_OUT / 4) + cx] = o;
        }
    }
}

// ---------------------------------------------------------------------------
// COO SpMM: dst[rows[e]] += vals[e] * src[cols[e]]   (dst pre-zeroed)
// 16 threads per edge-channel-group (float4 across 64 channels).
// Each group processes EPT=4 edges: batch index loads, batch independent
// gathers (MLP=4 outstanding L2 loads/thread), then batch red.v4 scatters.
// ---------------------------------------------------------------------------
#define EPT 4   // edges per thread-group

__global__ void __launch_bounds__(256) spmm_coo_kernel(
    const float* __restrict__ vals, const float4* __restrict__ src,
    float4* __restrict__ dst, int E)
{
    const int ch  = threadIdx.x & 15;            // float4 channel 0..15
    const int grp = threadIdx.x >> 4;            // edge group 0..15
    const int e0  = (blockIdx.x * 16 + grp) * EPT;

    int   r[EPT], c[EPT];
    float v[EPT];

    // Batch index/val loads (independent)
    #pragma unroll
    for (int j = 0; j < EPT; j++) {
        int e = e0 + j;
        if (e < E) {
            r[j] = g_rows[e];
            c[j] = g_cols[e];
            v[j] = vals[e];
        } else {
            r[j] = -1;
        }
    }

    // Batch gathers: EPT independent L2 loads in flight per thread
    float4 b[EPT];
    #pragma unroll
    for (int j = 0; j < EPT; j++)
        if (r[j] >= 0)
            b[j] = __ldg(src + (size_t)c[j] * (N_OUT / 4) + ch);

    // Batch scatters
    #pragma unroll
    for (int j = 0; j < EPT; j++) {
        if (r[j] >= 0) {
            float4* d = dst + (size_t)r[j] * (N_OUT / 4) + ch;
            asm volatile(
                "red.global.add.v4.f32 [%0], {%1, %2, %3, %4};"
                :: "l"(d), "f"(v[j] * b[j].x), "f"(v[j] * b[j].y),
                   "f"(v[j] * b[j].z), "f"(v[j] * b[j].w)
                : "memory");
        }
    }
}

// ---------------------------------------------------------------------------
// kernel_launch: detect -> decode -> GEMM -> (zero, SpMM) x3 ping-pong.
// Graph-capturable, allocation-free.
// ---------------------------------------------------------------------------
extern "C" void kernel_launch(void* const* d_in, const int* in_sizes, int n_in,
                              void* d_out, int out_size)
{
    const void*  adj  = d_in[0];                 // [2, E] int64 (detected)
    const float* vals = (const float*)d_in[1];   // [E]
    const float* X    = (const float*)d_in[2];   // [N, 256]
    const float* W    = (const float*)d_in[3];   // [256, 64]
    const float* bias = (const float*)d_in[4];   // [1, 64]
    float4*      out  = (float4*)d_out;          // [N, 64] fp32

    const int E = in_sizes[0] / 2;
    const int N = in_sizes[2] / N_IN;

    float4* bufA = nullptr;
    float4* bufB = nullptr;
    cudaGetSymbolAddress((void**)&bufA, g_bufA);
    cudaGetSymbolAddress((void**)&bufB, g_bufB);

    const size_t feat_bytes = (size_t)N * N_OUT * sizeof(float);

    // 0) dtype detect + index decode
    detect_dtype_kernel<<<1, 1>>>((const unsigned int*)adj);
    decode_kernel<<<(E + 255) / 256, 256>>>(adj, E);

    // 1) base = relu(X @ W + b) -> bufA
    gemm_bias_relu_kernel<<<(N + 63) / 64, 256>>>(X, W, bias, bufA, N);

    const int edges_per_block = 16 * EPT;
    const int spmm_blocks = (E + edges_per_block - 1) / edges_per_block;

    // 2) hop 1: bufA -> bufB
    cudaMemsetAsync(bufB, 0, feat_bytes, 0);
    spmm_coo_kernel<<<spmm_blocks, 256>>>(vals, bufA, bufB, E);

    // 3) hop 2: bufB -> bufA
    cudaMemsetAsync(bufA, 0, feat_bytes, 0);
    spmm_coo_kernel<<<spmm_blocks, 256>>>(vals, bufB, bufA, E);

    // 4) hop 3: bufA -> d_out
    cudaMemsetAsync(out, 0, feat_bytes, 0);
    spmm_coo_kernel<<<spmm_blocks, 256>>>(vals, bufA, out, E);
}

// round 5
// speedup vs baseline: 1.5562x; 1.3697x over previous
#include <cuda_runtime.h>
#include <cstdint>

#define N_IN   256
#define N_OUT  64
#define MAXN   100000
#define MAXE   1600000
#define SCAN_BS 512
#define MAX_SCAN_BLOCKS 256   // ceil(100000/512)=196 <= 256

// Scratch (allocation-free rule: __device__ globals). float4 => 16B aligned.
__device__ float4 g_bufA[(size_t)MAXN * N_OUT / 4];
__device__ float4 g_bufB[(size_t)MAXN * N_OUT / 4];
__device__ int2   g_csr[MAXE];          // (col, val-bits) sorted by row
__device__ int    g_deg[MAXN];
__device__ int    g_scanInc[MAXN];
__device__ int    g_rowptr[MAXN];       // exclusive scan (row start)
__device__ int    g_cursor[MAXN];       // scatter cursor; == row end after scatter
__device__ int    g_blockSums[MAX_SCAN_BLOCKS];
__device__ int    g_blockOff[MAX_SCAN_BLOCKS];
__device__ int    g_is64;

// ---------------------------------------------------------------------------
// Detect int64 vs int32 adj_index: for LE int64 < 2^32, odd words are zero.
// ---------------------------------------------------------------------------
__global__ void detect_dtype_kernel(const unsigned int* __restrict__ adj_words)
{
    unsigned int acc = 0;
    #pragma unroll
    for (int i = 1; i < 256; i += 2) acc |= adj_words[i];
    g_is64 = (acc == 0) ? 1 : 0;
}

__device__ __forceinline__ int load_idx(const void* adj, size_t i)
{
    return g_is64 ? (int)((const long long*)adj)[i] : ((const int*)adj)[i];
}

// ---------------------------------------------------------------------------
// CSR build step 1: row-degree histogram. g_deg pre-zeroed by memset.
// ---------------------------------------------------------------------------
__global__ void __launch_bounds__(256) histogram_kernel(const void* __restrict__ adj, int E)
{
    int i = blockIdx.x * blockDim.x + threadIdx.x;
    if (i >= E) return;
    atomicAdd(&g_deg[load_idx(adj, i)], 1);
}

// ---------------------------------------------------------------------------
// CSR build step 2a: per-block inclusive scan of g_deg (512 elems/block).
// ---------------------------------------------------------------------------
__global__ void __launch_bounds__(SCAN_BS) scan1_kernel(int N)
{
    __shared__ int s[SCAN_BS];
    int i = blockIdx.x * SCAN_BS + threadIdx.x;
    int v = (i < N) ? g_deg[i] : 0;
    s[threadIdx.x] = v;
    __syncthreads();
    #pragma unroll
    for (int off = 1; off < SCAN_BS; off <<= 1) {
        int t = (threadIdx.x >= off) ? s[threadIdx.x - off] : 0;
        __syncthreads();
        s[threadIdx.x] += t;
        __syncthreads();
    }
    if (i < N) g_scanInc[i] = s[threadIdx.x];
    if (threadIdx.x == SCAN_BS - 1) g_blockSums[blockIdx.x] = s[SCAN_BS - 1];
}

// ---------------------------------------------------------------------------
// CSR build step 2b: single-block exclusive scan of the block sums.
// ---------------------------------------------------------------------------
__global__ void __launch_bounds__(MAX_SCAN_BLOCKS) scan2_kernel(int NB)
{
    __shared__ int s[MAX_SCAN_BLOCKS];
    int v = (threadIdx.x < NB) ? g_blockSums[threadIdx.x] : 0;
    s[threadIdx.x] = v;
    __syncthreads();
    #pragma unroll
    for (int off = 1; off < MAX_SCAN_BLOCKS; off <<= 1) {
        int t = (threadIdx.x >= off) ? s[threadIdx.x - off] : 0;
        __syncthreads();
        s[threadIdx.x] += t;
        __syncthreads();
    }
    g_blockOff[threadIdx.x] = s[threadIdx.x] - v;   // exclusive
}

// ---------------------------------------------------------------------------
// CSR build step 2c: rowptr[i] = exclusive scan; init cursor = rowptr.
// ---------------------------------------------------------------------------
__global__ void __launch_bounds__(256) scan3_kernel(int N)
{
    int i = blockIdx.x * 256 + threadIdx.x;
    if (i < N) {
        int excl = g_scanInc[i] - g_deg[i] + g_blockOff[i >> 9];
        g_rowptr[i] = excl;
        g_cursor[i] = excl;
    }
}

// ---------------------------------------------------------------------------
// CSR build step 3: scatter edges into row-sorted order.
// After this kernel, g_cursor[row] == row end.
// ---------------------------------------------------------------------------
__global__ void __launch_bounds__(256) scatter_kernel(
    const void* __restrict__ adj, const float* __restrict__ vals, int E)
{
    int i = blockIdx.x * blockDim.x + threadIdx.x;
    if (i >= E) return;
    int row = load_idx(adj, i);
    int col = load_idx(adj, (size_t)E + i);
    int pos = atomicAdd(&g_cursor[row], 1);
    g_csr[pos] = make_int2(col, __float_as_int(vals[i]));
}

// ---------------------------------------------------------------------------
// Dense transform: out = relu(X @ W + bias). 64x64 tile, K by 64, ~33KB smem.
// ---------------------------------------------------------------------------
#define KC 64
#define XPAD 68

__global__ void __launch_bounds__(256) gemm_bias_relu_kernel(
    const float* __restrict__ X, const float* __restrict__ W,
    const float* __restrict__ bias, float4* __restrict__ out, int N)
{
    __shared__ float sW[KC * N_OUT];
    __shared__ float sX[64 * XPAD];

    const int tid  = threadIdx.x;
    const int row0 = blockIdx.x * 64;

    const int cx = tid & 15;
    const int ry = tid >> 4;

    float acc[4][4];
    #pragma unroll
    for (int i = 0; i < 4; i++)
        #pragma unroll
        for (int j = 0; j < 4; j++) acc[i][j] = 0.f;

    for (int k0 = 0; k0 < N_IN; k0 += KC) {
        #pragma unroll
        for (int i = tid; i < (KC * N_OUT) / 4; i += 256)
            ((float4*)sW)[i] = ((const float4*)(W + (size_t)k0 * N_OUT))[i];

        #pragma unroll
        for (int i = tid; i < 64 * 16; i += 256) {
            int r  = i >> 4;
            int kk = i & 15;
            float4 v = make_float4(0.f, 0.f, 0.f, 0.f);
            int row = row0 + r;
            if (row < N)
                v = ((const float4*)(X + (size_t)row * N_IN + k0))[kk];
            *((float4*)(sX + r * XPAD + kk * 4)) = v;
        }
        __syncthreads();

        const float* f0 = sX + (ry * 4 + 0) * XPAD;
        const float* f1 = sX + (ry * 4 + 1) * XPAD;
        const float* f2 = sX + (ry * 4 + 2) * XPAD;
        const float* f3 = sX + (ry * 4 + 3) * XPAD;

        #pragma unroll 8
        for (int k = 0; k < KC; k++) {
            float4 w = *(((const float4*)(sW + k * N_OUT)) + cx);
            float fa = f0[k], fb = f1[k], fc = f2[k], fd = f3[k];
            acc[0][0] += fa * w.x; acc[0][1] += fa * w.y; acc[0][2] += fa * w.z; acc[0][3] += fa * w.w;
            acc[1][0] += fb * w.x; acc[1][1] += fb * w.y; acc[1][2] += fb * w.z; acc[1][3] += fb * w.w;
            acc[2][0] += fc * w.x; acc[2][1] += fc * w.y; acc[2][2] += fc * w.z; acc[2][3] += fc * w.w;
            acc[3][0] += fd * w.x; acc[3][1] += fd * w.y; acc[3][2] += fd * w.z; acc[3][3] += fd * w.w;
        }
        __syncthreads();
    }

    float4 bb = ((const float4*)bias)[cx];
    #pragma unroll
    for (int i = 0; i < 4; i++) {
        int row = row0 + ry * 4 + i;
        if (row < N) {
            float4 o;
            o.x = fmaxf(acc[i][0] + bb.x, 0.f);
            o.y = fmaxf(acc[i][1] + bb.y, 0.f);
            o.z = fmaxf(acc[i][2] + bb.z, 0.f);
            o.w = fmaxf(acc[i][3] + bb.w, 0.f);
            out[(size_t)row * (N_OUT / 4) + cx] = o;
        }
    }
}

// ---------------------------------------------------------------------------
// CSR SpMM: dst[row] = sum_e val[e] * src[col[e]], atomic-free.
// 16 threads per row (float4 across 64 channels), 16 rows per 256-thr block.
// Inner loop unrolled x4 for MLP; single store per row (no memset needed).
// ---------------------------------------------------------------------------
__global__ void __launch_bounds__(256) spmm_csr_kernel(
    const float4* __restrict__ src, float4* __restrict__ dst, int N)
{
    const int ch  = threadIdx.x & 15;
    const int grp = threadIdx.x >> 4;
    const int row = blockIdx.x * 16 + grp;
    if (row >= N) return;

    int e   = g_rowptr[row];
    int end = g_cursor[row];   // == row end after scatter

    float4 acc = make_float4(0.f, 0.f, 0.f, 0.f);

    for (; e + 4 <= end; e += 4) {
        int2 p0 = g_csr[e + 0];
        int2 p1 = g_csr[e + 1];
        int2 p2 = g_csr[e + 2];
        int2 p3 = g_csr[e + 3];
        float4 b0 = __ldg(src + (size_t)p0.x * (N_OUT / 4) + ch);
        float4 b1 = __ldg(src + (size_t)p1.x * (N_OUT / 4) + ch);
        float4 b2 = __ldg(src + (size_t)p2.x * (N_OUT / 4) + ch);
        float4 b3 = __ldg(src + (size_t)p3.x * (N_OUT / 4) + ch);
        float v0 = __int_as_float(p0.y), v1 = __int_as_float(p1.y);
        float v2 = __int_as_float(p2.y), v3 = __int_as_float(p3.y);
        acc.x += v0 * b0.x + v1 * b1.x + v2 * b2.x + v3 * b3.x;
        acc.y += v0 * b0.y + v1 * b1.y + v2 * b2.y + v3 * b3.y;
        acc.z += v0 * b0.z + v1 * b1.z + v2 * b2.z + v3 * b3.z;
        acc.w += v0 * b0.w + v1 * b1.w + v2 * b2.w + v3 * b3.w;
    }
    for (; e < end; e++) {
        int2 p = g_csr[e];
        float4 b = __ldg(src + (size_t)p.x * (N_OUT / 4) + ch);
        float v = __int_as_float(p.y);
        acc.x += v * b.x; acc.y += v * b.y; acc.z += v * b.z; acc.w += v * b.w;
    }

    dst[(size_t)row * (N_OUT / 4) + ch] = acc;
}

// ---------------------------------------------------------------------------
// kernel_launch: detect -> CSR build -> GEMM -> SpMM x3 ping-pong.
// Graph-capturable, allocation-free.
// ---------------------------------------------------------------------------
extern "C" void kernel_launch(void* const* d_in, const int* in_sizes, int n_in,
                              void* d_out, int out_size)
{
    const void*  adj  = d_in[0];                 // [2, E] int64 (detected)
    const float* vals = (const float*)d_in[1];   // [E]
    const float* X    = (const float*)d_in[2];   // [N, 256]
    const float* W    = (const float*)d_in[3];   // [256, 64]
    const float* bias = (const float*)d_in[4];   // [1, 64]
    float4*      out  = (float4*)d_out;          // [N, 64] fp32

    const int E = in_sizes[0] / 2;
    const int N = in_sizes[2] / N_IN;

    float4* bufA = nullptr;
    float4* bufB = nullptr;
    int*    degp = nullptr;
    cudaGetSymbolAddress((void**)&bufA, g_bufA);
    cudaGetSymbolAddress((void**)&bufB, g_bufB);
    cudaGetSymbolAddress((void**)&degp, g_deg);

    // 0) dtype detect + CSR build
    detect_dtype_kernel<<<1, 1>>>((const unsigned int*)adj);
    cudaMemsetAsync(degp, 0, (size_t)N * sizeof(int), 0);
    histogram_kernel<<<(E + 255) / 256, 256>>>(adj, E);
    const int NB = (N + SCAN_BS - 1) / SCAN_BS;
    scan1_kernel<<<NB, SCAN_BS>>>(N);
    scan2_kernel<<<1, MAX_SCAN_BLOCKS>>>(NB);
    scan3_kernel<<<(N + 255) / 256, 256>>>(N);
    scatter_kernel<<<(E + 255) / 256, 256>>>(adj, vals, E);

    // 1) base = relu(X @ W + b) -> bufA
    gemm_bias_relu_kernel<<<(N + 63) / 64, 256>>>(X, W, bias, bufA, N);

    const int spmm_blocks = (N + 15) / 16;

    // 2) three atomic-free CSR SpMM hops, ping-pong
    spmm_csr_kernel<<<spmm_blocks, 256>>>(bufA, bufB, N);
    spmm_csr_kernel<<<spmm_blocks, 256>>>(bufB, bufA, N);
    spmm_csr_kernel<<<spmm_blocks, 256>>>(bufA, out, N);
}

// round 8
// speedup vs baseline: 1.8893x; 1.2141x over previous
#include <cuda_runtime.h>
#include <cstdint>

#define N_IN   256
#define N_OUT  64
#define MAXN   100000
#define MAXE   1600000
#define SCAN_BS 512
#define MAX_SCAN_BLOCKS 256

// Scratch (allocation-free rule: __device__ globals). float4 => 16B aligned.
__device__ float4 g_bufA[(size_t)MAXN * N_OUT / 4];
__device__ float4 g_bufB[(size_t)MAXN * N_OUT / 4];
__device__ float  g_WT[N_OUT * N_IN];   // W transposed: WT[n][k]
__device__ int2   g_csr[MAXE];
__device__ int    g_deg[MAXN];
__device__ int    g_scanInc[MAXN];
__device__ int    g_rowptr[MAXN];
__device__ int    g_cursor[MAXN];
__device__ int    g_blockSums[MAX_SCAN_BLOCKS];
__device__ int    g_blockOff[MAX_SCAN_BLOCKS];
__device__ int    g_is64;

// ===================== dtype detect + CSR build =============================
__global__ void detect_dtype_kernel(const unsigned int* __restrict__ adj_words)
{
    unsigned int acc = 0;
    #pragma unroll
    for (int i = 1; i < 256; i += 2) acc |= adj_words[i];
    g_is64 = (acc == 0) ? 1 : 0;
}

__device__ __forceinline__ int load_idx(const void* adj, size_t i)
{
    return g_is64 ? (int)((const long long*)adj)[i] : ((const int*)adj)[i];
}

__global__ void __launch_bounds__(256) histogram_kernel(const void* __restrict__ adj, int E)
{
    int i = blockIdx.x * blockDim.x + threadIdx.x;
    if (i >= E) return;
    atomicAdd(&g_deg[load_idx(adj, i)], 1);
}

__global__ void __launch_bounds__(SCAN_BS) scan1_kernel(int N)
{
    __shared__ int s[SCAN_BS];
    int i = blockIdx.x * SCAN_BS + threadIdx.x;
    int v = (i < N) ? g_deg[i] : 0;
    s[threadIdx.x] = v;
    __syncthreads();
    #pragma unroll
    for (int off = 1; off < SCAN_BS; off <<= 1) {
        int t = (threadIdx.x >= off) ? s[threadIdx.x - off] : 0;
        __syncthreads();
        s[threadIdx.x] += t;
        __syncthreads();
    }
    if (i < N) g_scanInc[i] = s[threadIdx.x];
    if (threadIdx.x == SCAN_BS - 1) g_blockSums[blockIdx.x] = s[SCAN_BS - 1];
}

__global__ void __launch_bounds__(MAX_SCAN_BLOCKS) scan2_kernel(int NB)
{
    __shared__ int s[MAX_SCAN_BLOCKS];
    int v = (threadIdx.x < NB) ? g_blockSums[threadIdx.x] : 0;
    s[threadIdx.x] = v;
    __syncthreads();
    #pragma unroll
    for (int off = 1; off < MAX_SCAN_BLOCKS; off <<= 1) {
        int t = (threadIdx.x >= off) ? s[threadIdx.x - off] : 0;
        __syncthreads();
        s[threadIdx.x] += t;
        __syncthreads();
    }
    g_blockOff[threadIdx.x] = s[threadIdx.x] - v;
}

__global__ void __launch_bounds__(256) scan3_kernel(int N)
{
    int i = blockIdx.x * 256 + threadIdx.x;
    if (i < N) {
        int excl = g_scanInc[i] - g_deg[i] + g_blockOff[i >> 9];
        g_rowptr[i] = excl;
        g_cursor[i] = excl;
    }
}

__global__ void __launch_bounds__(256) scatter_kernel(
    const void* __restrict__ adj, const float* __restrict__ vals, int E)
{
    int i = blockIdx.x * blockDim.x + threadIdx.x;
    if (i >= E) return;
    int row = load_idx(adj, i);
    int col = load_idx(adj, (size_t)E + i);
    int pos = atomicAdd(&g_cursor[row], 1);
    g_csr[pos] = make_int2(col, __float_as_int(vals[i]));
}

// W[256][64] -> WT[64][256]
__global__ void __launch_bounds__(256) transpose_w_kernel(const float* __restrict__ W)
{
    int i = blockIdx.x * 256 + threadIdx.x;   // i over 16384
    int n = i >> 8, k = i & 255;
    g_WT[n * N_IN + k] = W[k * N_OUT + n];
}

// ===================== tf32 mma.sync GEMM + bias + ReLU =====================
// out = relu(X @ W + bias). Per CTA: 128 rows x 64 cols.
// 8 warps, each warp: 16 rows x 64 cols via m16n8k8 tf32 mma.sync.
// K chunked by 32: sX[128][36] tf32-bits, sWT[64][36] tf32-bits.
// Bank map for fragments: (4*(lane>>2) + (lane&3)) % 32 == lane -> conflict-free.

__device__ __forceinline__ uint32_t f2tf32(float f)
{
    uint32_t u;
    asm("cvt.rna.tf32.f32 %0, %1;" : "=r"(u) : "f"(f));
    return u;
}

__device__ __forceinline__ void mma_tf32(float c[4], uint32_t a0, uint32_t a1,
                                         uint32_t a2, uint32_t a3,
                                         uint32_t b0, uint32_t b1)
{
    asm volatile(
        "mma.sync.aligned.m16n8k8.row.col.f32.tf32.tf32.f32 "
        "{%0,%1,%2,%3}, {%4,%5,%6,%7}, {%8,%9}, {%0,%1,%2,%3};"
        : "+f"(c[0]), "+f"(c[1]), "+f"(c[2]), "+f"(c[3])
        : "r"(a0), "r"(a1), "r"(a2), "r"(a3), "r"(b0), "r"(b1));
}

#define XS 36   // smem row stride (uint32) for both tiles

__global__ void __launch_bounds__(256) gemm_tf32_kernel(
    const float* __restrict__ X, const float* __restrict__ bias,
    float* __restrict__ out, int NN)
{
    __shared__ uint32_t sX[128 * XS];   // 18.4 KB
    __shared__ uint32_t sWT[64 * XS];   // 9.2 KB

    const int tid  = threadIdx.x;
    const int wid  = tid >> 5;
    const int lid  = tid & 31;
    const int gid  = lid >> 2;    // group id 0..7
    const int tig  = lid & 3;     // thread in group 0..3
    const int row0 = blockIdx.x * 128;
    const int wrow = wid * 16;    // warp's row offset within tile

    float c[8][4];
    #pragma unroll
    for (int nt = 0; nt < 8; nt++)
        #pragma unroll
        for (int j = 0; j < 4; j++) c[nt][j] = 0.f;

    for (int ch = 0; ch < 8; ch++) {
        const int k0 = ch * 32;

        // Stage X chunk: 128 rows x 32 k = 1024 float4, cvt to tf32 bits
        #pragma unroll
        for (int i = tid; i < 1024; i += 256) {
            int r = i >> 3, q = i & 7;
            float4 v = make_float4(0.f, 0.f, 0.f, 0.f);
            if (row0 + r < NN)
                v = ((const float4*)(X + (size_t)(row0 + r) * N_IN + k0))[q];
            uint4 u = make_uint4(f2tf32(v.x), f2tf32(v.y), f2tf32(v.z), f2tf32(v.w));
            *(uint4*)(sX + r * XS + q * 4) = u;
        }
        // Stage WT chunk: 64 n-rows x 32 k = 512 float4
        #pragma unroll
        for (int i = tid; i < 512; i += 256) {
            int n = i >> 3, q = i & 7;
            float4 v = ((const float4*)(g_WT + (size_t)n * N_IN + k0))[q];
            uint4 u = make_uint4(f2tf32(v.x), f2tf32(v.y), f2tf32(v.z), f2tf32(v.w));
            *(uint4*)(sWT + n * XS + q * 4) = u;
        }
        __syncthreads();

        #pragma unroll
        for (int ks = 0; ks < 4; ks++) {
            const int kb = ks * 8;
            // A fragment (16x8): rows wrow+gid / wrow+gid+8, cols kb+tig / kb+tig+4
            uint32_t a0 = sX[(wrow + gid)     * XS + kb + tig];
            uint32_t a1 = sX[(wrow + gid + 8) * XS + kb + tig];
            uint32_t a2 = sX[(wrow + gid)     * XS + kb + tig + 4];
            uint32_t a3 = sX[(wrow + gid + 8) * XS + kb + tig + 4];
            #pragma unroll
            for (int nt = 0; nt < 8; nt++) {
                // B fragment (8x8, col): n = nt*8+gid, k = kb+tig / kb+tig+4
                uint32_t b0 = sWT[(nt * 8 + gid) * XS + kb + tig];
                uint32_t b1 = sWT[(nt * 8 + gid) * XS + kb + tig + 4];
                mma_tf32(c[nt], a0, a1, a2, a3, b0, b1);
            }
        }
        __syncthreads();
    }

    // Epilogue: c0,c1 -> row_lo cols (2*tig, 2*tig+1); c2,c3 -> row_hi
    const int row_lo = row0 + wrow + gid;
    const int row_hi = row_lo + 8;
    #pragma unroll
    for (int nt = 0; nt < 8; nt++) {
        const int col = nt * 8 + tig * 2;
        const float b0 = __ldg(bias + col);
        const float b1 = __ldg(bias + col + 1);
        if (row_lo < NN) {
            float2 o = make_float2(fmaxf(c[nt][0] + b0, 0.f),
                                   fmaxf(c[nt][1] + b1, 0.f));
            *(float2*)(out + (size_t)row_lo * N_OUT + col) = o;
        }
        if (row_hi < NN) {
            float2 o = make_float2(fmaxf(c[nt][2] + b0, 0.f),
                                   fmaxf(c[nt][3] + b1, 0.f));
            *(float2*)(out + (size_t)row_hi * N_OUT + col) = o;
        }
    }
}

// ===================== CSR SpMM (atomic-free) ===============================
__global__ void __launch_bounds__(256) spmm_csr_kernel(
    const float4* __restrict__ src, float4* __restrict__ dst, int N)
{
    const int ch  = threadIdx.x & 15;
    const int grp = threadIdx.x >> 4;
    const int row = blockIdx.x * 16 + grp;
    if (row >= N) return;

    int e   = g_rowptr[row];
    int end = g_cursor[row];

    float4 acc = make_float4(0.f, 0.f, 0.f, 0.f);

    for (; e + 4 <= end; e += 4) {
        int2 p0 = g_csr[e + 0];
        int2 p1 = g_csr[e + 1];
        int2 p2 = g_csr[e + 2];
        int2 p3 = g_csr[e + 3];
        float4 b0 = __ldg(src + (size_t)p0.x * (N_OUT / 4) + ch);
        float4 b1 = __ldg(src + (size_t)p1.x * (N_OUT / 4) + ch);
        float4 b2 = __ldg(src + (size_t)p2.x * (N_OUT / 4) + ch);
        float4 b3 = __ldg(src + (size_t)p3.x * (N_OUT / 4) + ch);
        float v0 = __int_as_float(p0.y), v1 = __int_as_float(p1.y);
        float v2 = __int_as_float(p2.y), v3 = __int_as_float(p3.y);
        acc.x += v0 * b0.x + v1 * b1.x + v2 * b2.x + v3 * b3.x;
        acc.y += v0 * b0.y + v1 * b1.y + v2 * b2.y + v3 * b3.y;
        acc.z += v0 * b0.z + v1 * b1.z + v2 * b2.z + v3 * b3.z;
        acc.w += v0 * b0.w + v1 * b1.w + v2 * b2.w + v3 * b3.w;
    }
    for (; e < end; e++) {
        int2 p = g_csr[e];
        float4 b = __ldg(src + (size_t)p.x * (N_OUT / 4) + ch);
        float v = __int_as_float(p.y);
        acc.x += v * b.x; acc.y += v * b.y; acc.z += v * b.z; acc.w += v * b.w;
    }

    dst[(size_t)row * (N_OUT / 4) + ch] = acc;
}

// ===================== launch ===============================================
extern "C" void kernel_launch(void* const* d_in, const int* in_sizes, int n_in,
                              void* d_out, int out_size)
{
    const void*  adj  = d_in[0];
    const float* vals = (const float*)d_in[1];
    const float* X    = (const float*)d_in[2];
    const float* W    = (const float*)d_in[3];
    const float* bias = (const float*)d_in[4];
    float4*      out  = (float4*)d_out;

    const int E = in_sizes[0] / 2;
    const int N = in_sizes[2] / N_IN;

    float4* bufA = nullptr;
    float4* bufB = nullptr;
    int*    degp = nullptr;
    cudaGetSymbolAddress((void**)&bufA, g_bufA);
    cudaGetSymbolAddress((void**)&bufB, g_bufB);
    cudaGetSymbolAddress((void**)&degp, g_deg);

    // 0) dtype detect + W transpose + CSR build
    detect_dtype_kernel<<<1, 1>>>((const unsigned int*)adj);
    transpose_w_kernel<<<(N_IN * N_OUT + 255) / 256, 256>>>(W);
    cudaMemsetAsync(degp, 0, (size_t)N * sizeof(int), 0);
    histogram_kernel<<<(E + 255) / 256, 256>>>(adj, E);
    const int NB = (N + SCAN_BS - 1) / SCAN_BS;
    scan1_kernel<<<NB, SCAN_BS>>>(N);
    scan2_kernel<<<1, MAX_SCAN_BLOCKS>>>(NB);
    scan3_kernel<<<(N + 255) / 256, 256>>>(N);
    scatter_kernel<<<(E + 255) / 256, 256>>>(adj, vals, E);

    // 1) base = relu(X @ W + b) -> bufA   (tf32 mma.sync tensor cores)
    gemm_tf32_kernel<<<(N + 127) / 128, 256>>>(X, bias, (float*)bufA, N);

    const int spmm_blocks = (N + 15) / 16;

    // 2) three atomic-free CSR SpMM hops, ping-pong
    spmm_csr_kernel<<<spmm_blocks, 256>>>(bufA, bufB, N);
    spmm_csr_kernel<<<spmm_blocks, 256>>>(bufB, bufA, N);
    spmm_csr_kernel<<<spmm_blocks, 256>>>(bufA, out, N);
}